// round 16
// baseline (speedup 1.0000x reference)
#include <cuda_runtime.h>
#include <cuda_fp16.h>
#include <float.h>

#define Bv 4
#define Hv 8
#define BH 32
#define Nv 4096
#define Dv 64
#define Mv 64
#define NSPLIT 16
#define CHUNK 256
#define PW 68      // float-plane pitch (words)
#define PH 72      // half-plane pitch (halves)

#define NEG_INF __int_as_float(0xff800000)

typedef unsigned long long u64;

// ---- packed f32x2 helpers (u_kernel) ----
__device__ __forceinline__ u64 ffma2(u64 a, u64 b, u64 c) {
    u64 d;
    asm("fma.rn.f32x2 %0, %1, %2, %3;" : "=l"(d) : "l"(a), "l"(b), "l"(c));
    return d;
}
__device__ __forceinline__ float pairsum(u64 v) {
    unsigned lo, hi;
    asm("mov.b64 {%0, %1}, %2;" : "=r"(lo), "=r"(hi) : "l"(v));
    return __uint_as_float(lo) + __uint_as_float(hi);
}

// ---- tf32 mma helpers (inv kernel) ----
__device__ __forceinline__ unsigned cvt_tf32(float x) {
    unsigned u;
    asm("cvt.rna.tf32.f32 %0, %1;" : "=r"(u) : "f"(x));
    return u;
}
__device__ __forceinline__ void split_tf32(float x, unsigned& hi, unsigned& lo) {
    hi = cvt_tf32(x);
    lo = cvt_tf32(x - __uint_as_float(hi));
}
__device__ __forceinline__ void mma8(float c[4], const unsigned a[4], unsigned b0, unsigned b1) {
    asm("mma.sync.aligned.m16n8k8.row.col.f32.tf32.tf32.f32 "
        "{%0,%1,%2,%3},{%4,%5,%6,%7},{%8,%9},{%0,%1,%2,%3};"
        : "+f"(c[0]), "+f"(c[1]), "+f"(c[2]), "+f"(c[3])
        : "r"(a[0]), "r"(a[1]), "r"(a[2]), "r"(a[3]), "r"(b0), "r"(b1));
}
__device__ __forceinline__ void mma3(float c[4], const unsigned ah[4], const unsigned al[4],
                                     unsigned bh0, unsigned bh1, unsigned bl0, unsigned bl1) {
    mma8(c, ah, bh0, bh1);
    mma8(c, ah, bl0, bl1);
    mma8(c, al, bh0, bh1);
}
// ---- fp16 mma (m16n8k16) ----
__device__ __forceinline__ void mma16(float c[4], const unsigned a[4], unsigned b0, unsigned b1) {
    asm("mma.sync.aligned.m16n8k16.row.col.f32.f16.f16.f32 "
        "{%0,%1,%2,%3},{%4,%5,%6,%7},{%8,%9},{%0,%1,%2,%3};"
        : "+f"(c[0]), "+f"(c[1]), "+f"(c[2]), "+f"(c[3])
        : "r"(a[0]), "r"(a[1]), "r"(a[2]), "r"(a[3]), "r"(b0), "r"(b1));
}

// half split helpers
__device__ __forceinline__ void hsplit(float x, __half& h, __half& l) {
    h = __float2half_rn(x);
    l = __float2half_rn(x - __half2float(h));
}

// fp16 1-plane GEMM: A half plane, B single half plane
__device__ __forceinline__ void gemm16a(const __half* __restrict__ Ah,
                                        const __half* __restrict__ Bh,
                                        float c[4][4], int wn, int r0, int r1, int qr, int qc) {
    #pragma unroll
    for (int k16 = 0; k16 < 4; k16++) {
        int kb = k16 * 16 + 2 * qc;
        unsigned a[4];
        a[0] = *(const unsigned*)&Ah[r0 * PH + kb];
        a[1] = *(const unsigned*)&Ah[r1 * PH + kb];
        a[2] = *(const unsigned*)&Ah[r0 * PH + kb + 8];
        a[3] = *(const unsigned*)&Ah[r1 * PH + kb + 8];
        #pragma unroll
        for (int nt = 0; nt < 4; nt++) {
            int bn = wn * 32 + nt * 8 + qr;
            unsigned bh0 = *(const unsigned*)&Bh[bn * PH + kb];
            unsigned bh1 = *(const unsigned*)&Bh[bn * PH + kb + 8];
            mma16(c[nt], a, bh0, bh1);
        }
    }
}

// fp16 2-term GEMM: A half plane, B hi/lo half planes
__device__ __forceinline__ void gemm16b(const __half* __restrict__ Ah,
                                        const __half* __restrict__ Bh,
                                        const __half* __restrict__ Bl,
                                        float c[4][4], int wn, int r0, int r1, int qr, int qc) {
    #pragma unroll
    for (int k16 = 0; k16 < 4; k16++) {
        int kb = k16 * 16 + 2 * qc;
        unsigned a[4];
        a[0] = *(const unsigned*)&Ah[r0 * PH + kb];
        a[1] = *(const unsigned*)&Ah[r1 * PH + kb];
        a[2] = *(const unsigned*)&Ah[r0 * PH + kb + 8];
        a[3] = *(const unsigned*)&Ah[r1 * PH + kb + 8];
        #pragma unroll
        for (int nt = 0; nt < 4; nt++) {
            int bn = wn * 32 + nt * 8 + qr;
            unsigned bh0 = *(const unsigned*)&Bh[bn * PH + kb];
            unsigned bh1 = *(const unsigned*)&Bh[bn * PH + kb + 8];
            unsigned bl0 = *(const unsigned*)&Bl[bn * PH + kb];
            unsigned bl1 = *(const unsigned*)&Bl[bn * PH + kb + 8];
            mma16(c[nt], a, bh0, bh1);
            mma16(c[nt], a, bl0, bl1);
        }
    }
}

// fp16 3-term GEMM: A hi/lo, B hi/lo (scores path, ~22-bit accuracy)
__device__ __forceinline__ void gemm16_3(const __half* __restrict__ Ah, const __half* __restrict__ Al,
                                         const __half* __restrict__ Bh, const __half* __restrict__ Bl,
                                         float c[4][4], int wn, int r0, int r1, int qr, int qc) {
    #pragma unroll
    for (int k16 = 0; k16 < 4; k16++) {
        int kb = k16 * 16 + 2 * qc;
        unsigned ah[4], al[4];
        ah[0] = *(const unsigned*)&Ah[r0 * PH + kb];
        ah[1] = *(const unsigned*)&Ah[r1 * PH + kb];
        ah[2] = *(const unsigned*)&Ah[r0 * PH + kb + 8];
        ah[3] = *(const unsigned*)&Ah[r1 * PH + kb + 8];
        al[0] = *(const unsigned*)&Al[r0 * PH + kb];
        al[1] = *(const unsigned*)&Al[r1 * PH + kb];
        al[2] = *(const unsigned*)&Al[r0 * PH + kb + 8];
        al[3] = *(const unsigned*)&Al[r1 * PH + kb + 8];
        #pragma unroll
        for (int nt = 0; nt < 4; nt++) {
            int bn = wn * 32 + nt * 8 + qr;
            unsigned bh0 = *(const unsigned*)&Bh[bn * PH + kb];
            unsigned bh1 = *(const unsigned*)&Bh[bn * PH + kb + 8];
            unsigned bl0 = *(const unsigned*)&Bl[bn * PH + kb];
            unsigned bl1 = *(const unsigned*)&Bl[bn * PH + kb + 8];
            mma16(c[nt], ah, bh0, bh1);
            mma16(c[nt], ah, bl0, bl1);
            mma16(c[nt], al, bh0, bh1);
        }
    }
}

// ---------------- scratch ----------------
__device__ float  g_rs[2 * BH * Nv];
__device__ int    g_cidx[BH * Mv];
__device__ int    g_ridx[BH * Mv];
__device__ float  g_u[BH * Mv * Mv];
__device__ float  g_Vinv[BH * Mv * Mv];
__device__ float  g_Yp[(size_t)BH * NSPLIT * Mv * Dv];
__device__ float  g_mx[BH * NSPLIT * Mv];
__device__ float  g_sm[BH * NSPLIT * Mv];
__device__ float  g_Zt[BH * Mv * Dv];
__device__ __half g_Ph[(size_t)BH * Nv * Mv];
__device__ unsigned int g_gmax;

// ---------------- row sums (wide) + gmax reset ----------------
__global__ __launch_bounds__(256) void rowsum_kernel(const float* __restrict__ Kp,
                                                     const float* __restrict__ Qp,
                                                     const int* __restrict__ mask) {
    int bh = blockIdx.x, y = blockIdx.y;
    int b = bh / Hv;
    const float* T = (y == 0) ? Kp : Qp;
    const float* Tb = T + (size_t)bh * Nv * Dv;
    float* outs = g_rs + (y * BH + bh) * Nv;
    int base = blockIdx.z * 512;

    if (bh == 0 && y == 0 && blockIdx.z == 0 && threadIdx.x == 0) g_gmax = 0u;

    int hw = threadIdx.x >> 4, l16 = threadIdx.x & 15;
    for (int i = hw; i < 512; i += 16) {
        int r = base + i;
        float4 v4 = *(const float4*)(Tb + (size_t)r * Dv + l16 * 4);
        float v = (v4.x + v4.y) + (v4.z + v4.w);
        #pragma unroll
        for (int o = 1; o <= 8; o <<= 1) v += __shfl_xor_sync(0xffffffffu, v, o);
        if (l16 == 0) {
            bool bad = (r == 0) || (mask[b * Nv + r] != 0);
            outs[r] = bad ? -FLT_MAX : v;
        }
    }
}

// ---------------- top-k pick ----------------
__global__ __launch_bounds__(256) void pick_kernel() {
    int bh = blockIdx.x;
    int* outIdx = (blockIdx.y == 0) ? g_cidx : g_ridx;
    const float* ins = g_rs + (blockIdx.y * BH + bh) * Nv;

    __shared__ float s[Nv];
    __shared__ float cmax[16];
    __shared__ int   cidx[16];
    __shared__ int   picked[Mv];

    int tid = threadIdx.x;
    int warp = tid >> 5, lane = tid & 31;

    for (int i = tid; i < Nv / 4; i += 256)
        *(float4*)&s[i * 4] = *(const float4*)(ins + i * 4);
    __syncthreads();

    for (int c = warp; c < 16; c += 8) {
        float bv = -FLT_MAX; int bi = Nv;
        #pragma unroll
        for (int t = 0; t < 8; t++) {
            int idx = c * 256 + lane + 32 * t;
            float v = s[idx];
            if (v > bv || (v == bv && idx < bi)) { bv = v; bi = idx; }
        }
        #pragma unroll
        for (int o = 16; o; o >>= 1) {
            float ov = __shfl_xor_sync(0xffffffffu, bv, o);
            int   oi = __shfl_xor_sync(0xffffffffu, bi, o);
            if (ov > bv || (ov == bv && oi < bi)) { bv = ov; bi = oi; }
        }
        if (lane == 0) { cmax[c] = bv; cidx[c] = bi; }
    }
    __syncthreads();

    if (warp == 0) {
        for (int it = 0; it < Mv - 1; ++it) {
            float bv = (lane < 16) ? cmax[lane] : -FLT_MAX;
            int   bi = (lane < 16) ? cidx[lane] : Nv;
            #pragma unroll
            for (int o = 16; o; o >>= 1) {
                float ov = __shfl_xor_sync(0xffffffffu, bv, o);
                int   oi = __shfl_xor_sync(0xffffffffu, bi, o);
                if (ov > bv || (ov == bv && oi < bi)) { bv = ov; bi = oi; }
            }
            int gidx = __shfl_sync(0xffffffffu, bi, 0);
            if (lane == 0) { picked[it] = gidx; s[gidx] = -FLT_MAX; }
            __syncwarp();
            int c = gidx >> 8;
            float nv = -FLT_MAX; int ni = Nv;
            #pragma unroll
            for (int t = 0; t < 8; t++) {
                int idx = c * 256 + lane + 32 * t;
                float v = s[idx];
                if (v > nv || (v == nv && idx < ni)) { nv = v; ni = idx; }
            }
            #pragma unroll
            for (int o = 16; o; o >>= 1) {
                float ov = __shfl_xor_sync(0xffffffffu, nv, o);
                int   oi = __shfl_xor_sync(0xffffffffu, ni, o);
                if (ov > nv || (ov == nv && oi < ni)) { nv = ov; ni = oi; }
            }
            if (lane == 0) { cmax[c] = nv; cidx[c] = ni; }
            __syncwarp();
        }
        if (lane == 0) picked[Mv - 1] = 0;
    }
    __syncthreads();

    if (tid < Mv) {
        int key = picked[tid];
        int rank = 0;
        #pragma unroll 16
        for (int j = 0; j < Mv; j++) rank += (picked[j] < key);
        outIdx[bh * Mv + rank] = key;
    }
}

// ---------------- u = softmax(Qs[ridx] @ nc^T) + global colsum-max ----------
__global__ __launch_bounds__(256) void u_kernel(const float* __restrict__ Q,
                                                const float* __restrict__ K) {
    int bh = blockIdx.x;
    __shared__ float Kc[64 * PW];
    __shared__ float Qr[64 * PW];
    __shared__ float colsum[64];
    __shared__ int ci_s[64], ri_s[64];

    const float* Kb = K + (size_t)bh * Nv * Dv;
    const float* Qb = Q + (size_t)bh * Nv * Dv;
    int tid = threadIdx.x;
    if (tid < 64) { ci_s[tid] = g_cidx[bh * Mv + tid]; ri_s[tid] = g_ridx[bh * Mv + tid]; }
    __syncthreads();

    for (int idx = tid; idx < 64 * 16; idx += 256) {
        int r = idx >> 4, c4 = (idx & 15) * 4;
        float4 q4 = *(const float4*)(Qb + (size_t)ri_s[r] * Dv + c4);
        q4.x *= 0.125f; q4.y *= 0.125f; q4.z *= 0.125f; q4.w *= 0.125f;
        *(float4*)&Qr[r * PW + c4] = q4;
        *(float4*)&Kc[r * PW + c4] = *(const float4*)(Kb + (size_t)ci_s[r] * Dv + c4);
    }
    __syncthreads();

    int tx = tid & 15, ty = tid >> 4;
    u64 sc2[4][4];
    #pragma unroll
    for (int i = 0; i < 4; i++)
        #pragma unroll
        for (int j = 0; j < 4; j++) sc2[i][j] = 0ull;
    #pragma unroll 4
    for (int k4 = 0; k4 < 16; k4++) {
        ulonglong2 a2[4], b2[4];
        #pragma unroll
        for (int i = 0; i < 4; i++) a2[i] = *(const ulonglong2*)&Qr[(ty * 4 + i) * PW + k4 * 4];
        #pragma unroll
        for (int j = 0; j < 4; j++) b2[j] = *(const ulonglong2*)&Kc[(tx + 16 * j) * PW + k4 * 4];
        #pragma unroll
        for (int i = 0; i < 4; i++)
            #pragma unroll
            for (int j = 0; j < 4; j++) {
                sc2[i][j] = ffma2(a2[i].x, b2[j].x, sc2[i][j]);
                sc2[i][j] = ffma2(a2[i].y, b2[j].y, sc2[i][j]);
            }
    }
    __syncthreads();

    #pragma unroll
    for (int i = 0; i < 4; i++) {
        float sv[4];
        #pragma unroll
        for (int j = 0; j < 4; j++) sv[j] = pairsum(sc2[i][j]);
        float mx = fmaxf(fmaxf(sv[0], sv[1]), fmaxf(sv[2], sv[3]));
        #pragma unroll
        for (int o = 8; o; o >>= 1) mx = fmaxf(mx, __shfl_xor_sync(0xffffffffu, mx, o));
        float e[4], sm = 0.f;
        #pragma unroll
        for (int j = 0; j < 4; j++) { e[j] = __expf(sv[j] - mx); sm += e[j]; }
        #pragma unroll
        for (int o = 8; o; o >>= 1) sm += __shfl_xor_sync(0xffffffffu, sm, o);
        float inv = 1.f / sm;
        int row = ty * 4 + i;
        #pragma unroll
        for (int j = 0; j < 4; j++) {
            float p = e[j] * inv;
            Qr[row * PW + tx + 16 * j] = p;
            g_u[(bh * 64 + row) * 64 + tx + 16 * j] = p;
        }
    }
    __syncthreads();
    if (tid < 64) {
        float s = 0.f;
        #pragma unroll 8
        for (int i = 0; i < 64; i++) s += Qr[i * PW + tid];
        colsum[tid] = s;
    }
    __syncthreads();
    if (tid == 0) {
        float mx = colsum[0];
        for (int j = 1; j < 64; j++) mx = fmaxf(mx, colsum[j]);
        atomicMax(&g_gmax, __float_as_uint(mx));
    }
}

// ---------------- mm64v ----------------
__device__ __forceinline__ void mm64v(const float* __restrict__ A,
                                      const float* __restrict__ Bm,
                                      float acc[4][4], int tx, int ty) {
    #pragma unroll
    for (int i = 0; i < 4; i++)
        #pragma unroll
        for (int j = 0; j < 4; j++) acc[i][j] = 0.f;
    #pragma unroll 2
    for (int k4 = 0; k4 < 16; k4++) {
        float4 a[4];
        #pragma unroll
        for (int i = 0; i < 4; i++) a[i] = *(const float4*)&A[(ty * 4 + i) * 64 + k4 * 4];
        #pragma unroll
        for (int kk = 0; kk < 4; kk++) {
            float4 bv = *(const float4*)&Bm[(k4 * 4 + kk) * 64 + tx * 4];
            float av[4];
            av[0] = (kk == 0) ? a[0].x : (kk == 1) ? a[0].y : (kk == 2) ? a[0].z : a[0].w;
            av[1] = (kk == 0) ? a[1].x : (kk == 1) ? a[1].y : (kk == 2) ? a[1].z : a[1].w;
            av[2] = (kk == 0) ? a[2].x : (kk == 1) ? a[2].y : (kk == 2) ? a[2].z : a[2].w;
            av[3] = (kk == 0) ? a[3].x : (kk == 1) ? a[3].y : (kk == 2) ? a[3].z : a[3].w;
            #pragma unroll
            for (int i = 0; i < 4; i++) {
                acc[i][0] = fmaf(av[i], bv.x, acc[i][0]);
                acc[i][1] = fmaf(av[i], bv.y, acc[i][1]);
                acc[i][2] = fmaf(av[i], bv.z, acc[i][2]);
                acc[i][3] = fmaf(av[i], bv.w, acc[i][3]);
            }
        }
    }
}

// ---------------- Newton-Schulz inverse (3xTF32, inline split) ----------------
__device__ __forceinline__ void gemm3(const float* __restrict__ Arow, const float* __restrict__ Bt,
                                      float c[4][4], int wn, int r0, int r1, int qr, int qc) {
    #pragma unroll
    for (int nt = 0; nt < 4; nt++) { c[nt][0] = c[nt][1] = c[nt][2] = c[nt][3] = 0.f; }
    #pragma unroll
    for (int k8 = 0; k8 < 8; k8++) {
        int kb = k8 * 8;
        unsigned ah[4], al[4];
        split_tf32(Arow[r0 * PW + kb + qc],     ah[0], al[0]);
        split_tf32(Arow[r1 * PW + kb + qc],     ah[1], al[1]);
        split_tf32(Arow[r0 * PW + kb + 4 + qc], ah[2], al[2]);
        split_tf32(Arow[r1 * PW + kb + 4 + qc], ah[3], al[3]);
        #pragma unroll
        for (int nt = 0; nt < 4; nt++) {
            int bn = wn * 32 + nt * 8 + qr;
            unsigned bh0, bl0, bh1, bl1;
            split_tf32(Bt[bn * PW + kb + qc],     bh0, bl0);
            split_tf32(Bt[bn * PW + kb + 4 + qc], bh1, bl1);
            mma3(c[nt], ah, al, bh0, bh1, bl0, bl1);
        }
    }
}

extern __shared__ float invsm[];
__global__ __launch_bounds__(256) void inv_kernel() {
    float* Us  = invsm;
    float* Vr  = Us  + 64 * PW;
    float* Vt  = Vr  + 64 * PW;
    float* Ar  = Vt  + 64 * PW;
    float* At  = Ar  + 64 * PW;
    float* Tt  = At  + 64 * PW;
    float* T2t = Tt  + 64 * PW;

    int bh = blockIdx.x, tid = threadIdx.x;
    int wid = tid >> 5, lane = tid & 31;
    int wm = wid & 3, wn = wid >> 2;
    int qr = lane >> 2, qc = lane & 3;
    int r0 = wm * 16 + qr, r1 = r0 + 8;

    const float* Ug = g_u + (size_t)bh * 4096;
    float ginv = 1.f / __uint_as_float(g_gmax);

    for (int idx = tid; idx < 1024; idx += 256) {
        int r = idx >> 4, c4 = (idx & 15) * 4;
        float4 u4 = *(const float4*)(Ug + r * 64 + c4);
        *(float4*)&Us[r * PW + c4] = u4;
        float4 s4 = make_float4(u4.x * ginv, u4.y * ginv, u4.z * ginv, u4.w * ginv);
        *(float4*)&Vt[r * PW + c4] = s4;
        Vr[(c4 + 0) * PW + r] = s4.x;
        Vr[(c4 + 1) * PW + r] = s4.y;
        Vr[(c4 + 2) * PW + r] = s4.z;
        Vr[(c4 + 3) * PW + r] = s4.w;
    }
    __syncthreads();

    float c1[4][4], cw[4][4];
    for (int it = 0; it < 6; it++) {
        gemm3(Us, Vt, c1, wn, r0, r1, qr, qc);
        #pragma unroll
        for (int nt = 0; nt < 4; nt++) {
            int c0 = wn * 32 + nt * 8 + 2 * qc;
            Ar[r0 * PW + c0] = c1[nt][0]; Ar[r0 * PW + c0 + 1] = c1[nt][1];
            Ar[r1 * PW + c0] = c1[nt][2]; Ar[r1 * PW + c0 + 1] = c1[nt][3];
            At[c0 * PW + r0] = c1[nt][0]; At[(c0 + 1) * PW + r0] = c1[nt][1];
            At[c0 * PW + r1] = c1[nt][2]; At[(c0 + 1) * PW + r1] = c1[nt][3];
        }
        __syncthreads();

        gemm3(Ar, At, cw, wn, r0, r1, qr, qc);
        #pragma unroll
        for (int nt = 0; nt < 4; nt++) {
            int c0 = wn * 32 + nt * 8 + 2 * qc;
            Tt[c0 * PW + r0]       = 7.f * c1[nt][0] - cw[nt][0];
            Tt[(c0 + 1) * PW + r0] = 7.f * c1[nt][1] - cw[nt][1];
            Tt[c0 * PW + r1]       = 7.f * c1[nt][2] - cw[nt][2];
            Tt[(c0 + 1) * PW + r1] = 7.f * c1[nt][3] - cw[nt][3];
        }
        __syncthreads();

        gemm3(Ar, Tt, cw, wn, r0, r1, qr, qc);
        #pragma unroll
        for (int nt = 0; nt < 4; nt++) {
            int c0 = wn * 32 + nt * 8 + 2 * qc;
            T2t[c0 * PW + r0]       = 15.f * c1[nt][0] - cw[nt][0];
            T2t[(c0 + 1) * PW + r0] = 15.f * c1[nt][1] - cw[nt][1];
            T2t[c0 * PW + r1]       = 15.f * c1[nt][2] - cw[nt][2];
            T2t[(c0 + 1) * PW + r1] = 15.f * c1[nt][3] - cw[nt][3];
        }
        __syncthreads();

        gemm3(Vr, T2t, cw, wn, r0, r1, qr, qc);
        __syncthreads();
        #pragma unroll
        for (int nt = 0; nt < 4; nt++) {
            int c0 = wn * 32 + nt * 8 + 2 * qc;
            float v00 = Vr[r0 * PW + c0], v01 = Vr[r0 * PW + c0 + 1];
            float v10 = Vr[r1 * PW + c0], v11 = Vr[r1 * PW + c0 + 1];
            float n00 = 0.25f * (13.f * v00 - cw[nt][0]);
            float n01 = 0.25f * (13.f * v01 - cw[nt][1]);
            float n10 = 0.25f * (13.f * v10 - cw[nt][2]);
            float n11 = 0.25f * (13.f * v11 - cw[nt][3]);
            Vr[r0 * PW + c0] = n00; Vr[r0 * PW + c0 + 1] = n01;
            Vr[r1 * PW + c0] = n10; Vr[r1 * PW + c0 + 1] = n11;
            Vt[c0 * PW + r0] = n00; Vt[(c0 + 1) * PW + r0] = n01;
            Vt[c0 * PW + r1] = n10; Vt[(c0 + 1) * PW + r1] = n11;
        }
        __syncthreads();
    }

    for (int idx = tid; idx < 1024; idx += 256) {
        int r = idx >> 4, c4 = (idx & 15) * 4;
        *(float4*)(g_Vinv + (size_t)bh * 4096 + r * 64 + c4) = *(float4*)&Vr[r * PW + c4];
    }
}

// ---------------- flash: S via fp16 3-term, PV via fp16 1-plane V ----------
extern __shared__ float fsmem[];
__global__ __launch_bounds__(256, 4) void flash_kernel(const float* __restrict__ Q,
                                                       const float* __restrict__ K,
                                                       const float* __restrict__ V,
                                                       const int* __restrict__ mask) {
    __half* Qh = (__half*)fsmem;            // nr hi [m][d]
    __half* Ql = Qh + 64 * PH;              // nr lo
    __half* Ph = Ql + 64 * PH;              // P [m][n]
    __half* Bh = Ph + 64 * PH;              // K hi [n][d], then V hi [d][n]
    __half* Bl = Bh + 64 * PH;              // K lo (scores only)
    __shared__ float rmaxp[2][64];
    __shared__ float rsump[2][64];
    __shared__ int msk[64];
    __shared__ int ri_s[64];

    int bh = blockIdx.y, sp = blockIdx.x;
    int b = bh / Hv;
    const float* Qb = Q + (size_t)bh * Nv * Dv;
    const float* Kb = K + (size_t)bh * Nv * Dv;
    const float* Vb = V + (size_t)bh * Nv * Dv;

    int tid = threadIdx.x;
    int wid = tid >> 5, lane = tid & 31;
    int wm = wid & 3, wn = wid >> 2;
    int qr = lane >> 2, qc = lane & 3;
    int r0 = wm * 16 + qr, r1 = r0 + 8;

    if (tid < 64) ri_s[tid] = g_ridx[bh * Mv + tid];
    __syncthreads();
    for (int idx = tid; idx < 64 * 16; idx += 256) {
        int r = idx >> 4, c4 = (idx & 15) * 4;
        float4 q4 = *(const float4*)(Qb + (size_t)ri_s[r] * Dv + c4);
        __half h, l;
        hsplit(q4.x * 0.125f, h, l); Qh[r * PH + c4 + 0] = h; Ql[r * PH + c4 + 0] = l;
        hsplit(q4.y * 0.125f, h, l); Qh[r * PH + c4 + 1] = h; Ql[r * PH + c4 + 1] = l;
        hsplit(q4.z * 0.125f, h, l); Qh[r * PH + c4 + 2] = h; Ql[r * PH + c4 + 2] = l;
        hsplit(q4.w * 0.125f, h, l); Qh[r * PH + c4 + 3] = h; Ql[r * PH + c4 + 3] = l;
    }

    float o[4][4];
    #pragma unroll
    for (int nt = 0; nt < 4; nt++)
        #pragma unroll
        for (int j = 0; j < 4; j++) o[nt][j] = 0.f;
    float m0 = NEG_INF, m1 = NEG_INF, l0 = 0.f, l1 = 0.f;

    int base0 = sp * CHUNK;
    for (int t = 0; t < CHUNK / 64; t++) {
        int base = base0 + t * 64;
        __syncthreads();                       // B planes + Ph free; Q ready on t=0
        for (int idx = tid; idx < 64 * 16; idx += 256) {
            int r = idx >> 4, c4 = (idx & 15) * 4;
            float4 k4 = *(const float4*)(Kb + (size_t)(base + r) * Dv + c4);
            __half h, l;
            hsplit(k4.x, h, l); Bh[r * PH + c4 + 0] = h; Bl[r * PH + c4 + 0] = l;
            hsplit(k4.y, h, l); Bh[r * PH + c4 + 1] = h; Bl[r * PH + c4 + 1] = l;
            hsplit(k4.z, h, l); Bh[r * PH + c4 + 2] = h; Bl[r * PH + c4 + 2] = l;
            hsplit(k4.w, h, l); Bh[r * PH + c4 + 3] = h; Bl[r * PH + c4 + 3] = l;
        }
        if (tid < 64) msk[tid] = mask[b * Nv + base + tid];
        __syncthreads();

        // ---- S = nr @ K^T (fp16 3-term) ----
        float s[4][4];
        #pragma unroll
        for (int nt = 0; nt < 4; nt++)
            #pragma unroll
            for (int j = 0; j < 4; j++) s[nt][j] = 0.f;
        gemm16_3(Qh, Ql, Bh, Bl, s, wn, r0, r1, qr, qc);

        // ---- mask + row max ----
        float rmA = NEG_INF, rmB = NEG_INF;
        #pragma unroll
        for (int nt = 0; nt < 4; nt++) {
            int c0 = wn * 32 + nt * 8 + 2 * qc, c1c = c0 + 1;
            if (!msk[c0])  { s[nt][0] = NEG_INF; s[nt][2] = NEG_INF; }
            if (!msk[c1c]) { s[nt][1] = NEG_INF; s[nt][3] = NEG_INF; }
            rmA = fmaxf(rmA, fmaxf(s[nt][0], s[nt][1]));
            rmB = fmaxf(rmB, fmaxf(s[nt][2], s[nt][3]));
        }
        #pragma unroll
        for (int o2 = 1; o2 <= 2; o2 <<= 1) {
            rmA = fmaxf(rmA, __shfl_xor_sync(0xffffffffu, rmA, o2));
            rmB = fmaxf(rmB, __shfl_xor_sync(0xffffffffu, rmB, o2));
        }
        if (qc == 0) { rmaxp[wn][r0] = rmA; rmaxp[wn][r1] = rmB; }
        __syncthreads();                       // S reads of K planes done

        // ---- V tile -> Bh plane only (transposed, fp16 hi) + online softmax ----
        for (int idx = tid; idx < 64 * 16; idx += 256) {
            int r = idx & 63, c4 = (idx >> 6) * 4;
            float4 v = *(const float4*)(Vb + (size_t)(base + r) * Dv + c4);
            Bh[(c4 + 0) * PH + r] = __float2half_rn(v.x);
            Bh[(c4 + 1) * PH + r] = __float2half_rn(v.y);
            Bh[(c4 + 2) * PH + r] = __float2half_rn(v.z);
            Bh[(c4 + 3) * PH + r] = __float2half_rn(v.w);
        }
        float tmxA = fmaxf(rmaxp[0][r0], rmaxp[1][r0]);
        float tmxB = fmaxf(rmaxp[0][r1], rmaxp[1][r1]);
        float nmA = fmaxf(m0, tmxA), mcA = fmaxf(nmA, -1e30f);
        float nmB = fmaxf(m1, tmxB), mcB = fmaxf(nmB, -1e30f);
        float alA = __expf(m0 - mcA), alB = __expf(m1 - mcB);
        m0 = nmA; m1 = nmB;
        float tsA = 0.f, tsB = 0.f;
        #pragma unroll
        for (int nt = 0; nt < 4; nt++) {
            int c0 = wn * 32 + nt * 8 + 2 * qc;
            float p00 = __expf(s[nt][0] - mcA), p01 = __expf(s[nt][1] - mcA);
            float p10 = __expf(s[nt][2] - mcB), p11 = __expf(s[nt][3] - mcB);
            tsA += p00 + p01; tsB += p10 + p11;
            *(half2*)&Ph[r0 * PH + c0] = __floats2half2_rn(p00, p01);
            *(half2*)&Ph[r1 * PH + c0] = __floats2half2_rn(p10, p11);
        }
        #pragma unroll
        for (int o2 = 1; o2 <= 2; o2 <<= 1) {
            tsA += __shfl_xor_sync(0xffffffffu, tsA, o2);
            tsB += __shfl_xor_sync(0xffffffffu, tsB, o2);
        }
        l0 = l0 * alA + tsA;
        l1 = l1 * alB + tsB;
        #pragma unroll
        for (int nt = 0; nt < 4; nt++) {
            o[nt][0] *= alA; o[nt][1] *= alA;
            o[nt][2] *= alB; o[nt][3] *= alB;
        }
        __syncthreads();                       // P + V plane ready

        // ---- O += P @ V (fp16, single V plane) ----
        gemm16a(Ph, Bh, o, wn, r0, r1, qr, qc);
    }

    if (qc == 0) { rsump[wn][r0] = l0; rsump[wn][r1] = l1; }
    int idxbase = (bh * NSPLIT + sp) * 64;
    if (wn == 0 && qc == 0) {
        g_mx[idxbase + r0] = m0;
        g_mx[idxbase + r1] = m1;
    }
    __syncthreads();
    if (tid < 64) g_sm[idxbase + tid] = rsump[0][tid] + rsump[1][tid];
    #pragma unroll
    for (int nt = 0; nt < 4; nt++) {
        int c0 = wn * 32 + nt * 8 + 2 * qc;
        *(float2*)&g_Yp[((size_t)idxbase + r0) * 64 + c0] = make_float2(o[nt][0], o[nt][1]);
        *(float2*)&g_Yp[((size_t)idxbase + r1) * 64 + c0] = make_float2(o[nt][2], o[nt][3]);
    }
}

// ---------------- fused: combine split partials -> Y (smem), Zt = (Vinv@Y)^T --
__global__ __launch_bounds__(256) void combine_z_kernel() {
    __shared__ float Vv[4096];
    __shared__ float Ys[4096];
    int bh = blockIdx.x, tid = threadIdx.x;

    for (int i = tid; i < 4096; i += 256) Vv[i] = g_Vinv[(size_t)bh * 4096 + i];

    int mrow = tid >> 4;              // 0..15
    int dq = (tid & 15) * 4;
    #pragma unroll
    for (int g = 0; g < 4; g++) {
        int m = g * 16 + mrow;
        float mx = NEG_INF;
        #pragma unroll
        for (int s = 0; s < NSPLIT; s++)
            mx = fmaxf(mx, g_mx[(bh * NSPLIT + s) * 64 + m]);
        float mc = fmaxf(mx, -1e30f);
        float tot = 0.f;
        float4 acc = make_float4(0.f, 0.f, 0.f, 0.f);
        #pragma unroll 4
        for (int s = 0; s < NSPLIT; s++) {
            float w = __expf(g_mx[(bh * NSPLIT + s) * 64 + m] - mc);
            tot += w * g_sm[(bh * NSPLIT + s) * 64 + m];
            float4 yp = *(const float4*)(g_Yp + (((size_t)(bh * NSPLIT + s) * 64) + m) * 64 + dq);
            acc.x += w * yp.x; acc.y += w * yp.y; acc.z += w * yp.z; acc.w += w * yp.w;
        }
        float inv = 1.f / tot;
        *(float4*)&Ys[m * 64 + dq] =
            make_float4(acc.x * inv, acc.y * inv, acc.z * inv, acc.w * inv);
    }
    __syncthreads();

    int tx = tid & 15, ty = tid >> 4;
    float a2[4][4];
    mm64v(Vv, Ys, a2, tx, ty);
    #pragma unroll
    for (int i = 0; i < 4; i++)
        #pragma unroll
        for (int j = 0; j < 4; j++)
            g_Zt[(size_t)bh * 4096 + (tx * 4 + j) * 64 + ty * 4 + i] = a2[i][j];
}

// ---------------- fxS: P = softmax(Qs @ nc^T) (fp16 3-term scores) -> g_Ph ----
extern __shared__ float xssm[];
__global__ __launch_bounds__(256, 4) void fxs_kernel(const float* __restrict__ Q,
                                                     const float* __restrict__ K) {
    __half* Qh = (__half*)xssm;            // [n][d] hi
    __half* Ql = Qh + 64 * PH;             // lo
    __half* Bh = Ql + 64 * PH;             // nc hi
    __half* Bl = Bh + 64 * PH;             // nc lo
    __shared__ float rmaxp[2][64];
    __shared__ float rsump[2][64];
    __shared__ int ci_s[64];

    int bh = blockIdx.y; int n0 = blockIdx.x * 64;
    const float* Kb = K + (size_t)bh * Nv * Dv;
    const float* Qb = Q + (size_t)bh * Nv * Dv;
    int tid = threadIdx.x;
    int wid = tid >> 5, lane = tid & 31;
    int wm = wid & 3, wn = wid >> 2;
    int qr = lane >> 2, qc = lane & 3;
    int r0 = wm * 16 + qr, r1 = r0 + 8;

    if (tid < 64) ci_s[tid] = g_cidx[bh * Mv + tid];
    __syncthreads();

    for (int idx = tid; idx < 64 * 16; idx += 256) {
        int r = idx >> 4, c4 = (idx & 15) * 4;
        float4 q4 = *(const float4*)(Qb + (size_t)(n0 + r) * Dv + c4);
        __half h, l;
        hsplit(q4.x * 0.125f, h, l); Qh[r * PH + c4 + 0] = h; Ql[r * PH + c4 + 0] = l;
        hsplit(q4.y * 0.125f, h, l); Qh[r * PH + c4 + 1] = h; Ql[r * PH + c4 + 1] = l;
        hsplit(q4.z * 0.125f, h, l); Qh[r * PH + c4 + 2] = h; Ql[r * PH + c4 + 2] = l;
        hsplit(q4.w * 0.125f, h, l); Qh[r * PH + c4 + 3] = h; Ql[r * PH + c4 + 3] = l;
        float4 n4 = *(const float4*)(Kb + (size_t)ci_s[r] * Dv + c4);
        hsplit(n4.x, h, l); Bh[r * PH + c4 + 0] = h; Bl[r * PH + c4 + 0] = l;
        hsplit(n4.y, h, l); Bh[r * PH + c4 + 1] = h; Bl[r * PH + c4 + 1] = l;
        hsplit(n4.z, h, l); Bh[r * PH + c4 + 2] = h; Bl[r * PH + c4 + 2] = l;
        hsplit(n4.w, h, l); Bh[r * PH + c4 + 3] = h; Bl[r * PH + c4 + 3] = l;
    }
    __syncthreads();

    float s[4][4];
    #pragma unroll
    for (int nt = 0; nt < 4; nt++)
        #pragma unroll
        for (int j = 0; j < 4; j++) s[nt][j] = 0.f;
    gemm16_3(Qh, Ql, Bh, Bl, s, wn, r0, r1, qr, qc);

    float rmA = NEG_INF, rmB = NEG_INF;
    #pragma unroll
    for (int nt = 0; nt < 4; nt++) {
        rmA = fmaxf(rmA, fmaxf(s[nt][0], s[nt][1]));
        rmB = fmaxf(rmB, fmaxf(s[nt][2], s[nt][3]));
    }
    #pragma unroll
    for (int o2 = 1; o2 <= 2; o2 <<= 1) {
        rmA = fmaxf(rmA, __shfl_xor_sync(0xffffffffu, rmA, o2));
        rmB = fmaxf(rmB, __shfl_xor_sync(0xffffffffu, rmB, o2));
    }
    if (qc == 0) { rmaxp[wn][r0] = rmA; rmaxp[wn][r1] = rmB; }
    __syncthreads();

    float mcA = fmaxf(rmaxp[0][r0], rmaxp[1][r0]);
    float mcB = fmaxf(rmaxp[0][r1], rmaxp[1][r1]);
    float p[4][4];
    float tsA = 0.f, tsB = 0.f;
    #pragma unroll
    for (int nt = 0; nt < 4; nt++) {
        p[nt][0] = __expf(s[nt][0] - mcA); p[nt][1] = __expf(s[nt][1] - mcA);
        p[nt][2] = __expf(s[nt][2] - mcB); p[nt][3] = __expf(s[nt][3] - mcB);
        tsA += p[nt][0] + p[nt][1]; tsB += p[nt][2] + p[nt][3];
    }
    #pragma unroll
    for (int o2 = 1; o2 <= 2; o2 <<= 1) {
        tsA += __shfl_xor_sync(0xffffffffu, tsA, o2);
        tsB += __shfl_xor_sync(0xffffffffu, tsB, o2);
    }
    if (qc == 0) { rsump[wn][r0] = tsA; rsump[wn][r1] = tsB; }
    __syncthreads();

    float invA = 1.f / (rsump[0][r0] + rsump[1][r0]);
    float invB = 1.f / (rsump[0][r1] + rsump[1][r1]);
    __half* Pg = g_Ph + (size_t)bh * Nv * Mv;
    #pragma unroll
    for (int nt = 0; nt < 4; nt++) {
        int c0 = wn * 32 + nt * 8 + 2 * qc;
        *(half2*)(Pg + (size_t)(n0 + r0) * Mv + c0) = __floats2half2_rn(p[nt][0] * invA, p[nt][1] * invA);
        *(half2*)(Pg + (size_t)(n0 + r1) * Mv + c0) = __floats2half2_rn(p[nt][2] * invB, p[nt][3] * invB);
    }
}

// ---------------- fxZ: X = P @ Z (fp16, Z hi/lo) ----------------
extern __shared__ float xzsm[];
__global__ __launch_bounds__(256, 4) void fxz_kernel(float* __restrict__ out) {
    __half* Pp = (__half*)xzsm;                     // [n][m'] half, pitch PH
    __half* Zh = Pp + 64 * PH;                      // [d][m'] half hi
    __half* Zl = Zh + 64 * PH;                      // [d][m'] half lo

    int bh = blockIdx.y; int n0 = blockIdx.x * 64;
    int tid = threadIdx.x;
    int wid = tid >> 5, lane = tid & 31;
    int wm = wid & 3, wn = wid >> 2;
    int qr = lane >> 2, qc = lane & 3;
    int r0 = wm * 16 + qr, r1 = r0 + 8;

    const __half* Pg = g_Ph + (size_t)bh * Nv * Mv;
    for (int idx = tid; idx < 64 * 8; idx += 256) {
        int r = idx >> 3, c8 = (idx & 7) * 8;
        *(uint4*)&Pp[r * PH + c8] = *(const uint4*)(Pg + (size_t)(n0 + r) * Mv + c8);
    }
    for (int idx = tid; idx < 64 * 16; idx += 256) {
        int r = idx >> 4, c4 = (idx & 15) * 4;
        float4 z4 = *(const float4*)(g_Zt + (size_t)bh * 4096 + r * 64 + c4);
        __half h, l;
        hsplit(z4.x, h, l); Zh[r * PH + c4 + 0] = h; Zl[r * PH + c4 + 0] = l;
        hsplit(z4.y, h, l); Zh[r * PH + c4 + 1] = h; Zl[r * PH + c4 + 1] = l;
        hsplit(z4.z, h, l); Zh[r * PH + c4 + 2] = h; Zl[r * PH + c4 + 2] = l;
        hsplit(z4.w, h, l); Zh[r * PH + c4 + 3] = h; Zl[r * PH + c4 + 3] = l;
    }
    __syncthreads();

    float o[4][4];
    #pragma unroll
    for (int nt = 0; nt < 4; nt++)
        #pragma unroll
        for (int j = 0; j < 4; j++) o[nt][j] = 0.f;
    gemm16b(Pp, Zh, Zl, o, wn, r0, r1, qr, qc);

    #pragma unroll
    for (int nt = 0; nt < 4; nt++) {
        int c0 = wn * 32 + nt * 8 + 2 * qc;
        *(float2*)(out + ((size_t)bh * Nv + n0 + r0) * Dv + c0) = make_float2(o[nt][0], o[nt][1]);
        *(float2*)(out + ((size_t)bh * Nv + n0 + r1) * Dv + c0) = make_float2(o[nt][2], o[nt][3]);
    }
}

// ---------------- launch ----------------
extern "C" void kernel_launch(void* const* d_in, const int* in_sizes, int n_in,
                              void* d_out, int out_size) {
    (void)in_sizes; (void)n_in; (void)out_size;
    const float* Q    = (const float*)d_in[0];
    const float* K    = (const float*)d_in[1];
    const float* V    = (const float*)d_in[2];
    const int*   mask = (const int*)d_in[3];
    float* out = (float*)d_out;

    const int FLASH_SMEM = 5 * 64 * PH * 2;                  // 46080 -> 4 CTAs/SM
    const int FXS_SMEM   = 4 * 64 * PH * 2;                  // 36864
    const int FXZ_SMEM   = 3 * 64 * PH * 2;                  // 27648
    const int INV_SMEM   = 7 * 64 * PW * (int)sizeof(float); // 121856

    static bool init_done = false;
    static cudaStream_t s2, s3;
    static cudaEvent_t evPick, evInv, evS;
    if (!init_done) {
        cudaFuncSetAttribute(flash_kernel, cudaFuncAttributeMaxDynamicSharedMemorySize, FLASH_SMEM);
        cudaFuncSetAttribute(fxs_kernel, cudaFuncAttributeMaxDynamicSharedMemorySize, FXS_SMEM);
        cudaFuncSetAttribute(fxz_kernel, cudaFuncAttributeMaxDynamicSharedMemorySize, FXZ_SMEM);
        cudaFuncSetAttribute(inv_kernel, cudaFuncAttributeMaxDynamicSharedMemorySize, INV_SMEM);
        cudaStreamCreateWithFlags(&s2, cudaStreamNonBlocking);
        cudaStreamCreateWithFlags(&s3, cudaStreamNonBlocking);
        cudaEventCreateWithFlags(&evPick, cudaEventDisableTiming);
        cudaEventCreateWithFlags(&evInv, cudaEventDisableTiming);
        cudaEventCreateWithFlags(&evS, cudaEventDisableTiming);
        init_done = true;
    }

    rowsum_kernel<<<dim3(BH, 2, 8), 256>>>(K, Q, mask);        // launch 1
    pick_kernel<<<dim3(BH, 2), 256>>>();                       // launch 2
    cudaEventRecord(evPick, 0);

    // s2: u -> inv (overlaps flash)
    cudaStreamWaitEvent(s2, evPick, 0);
    u_kernel<<<BH, 256, 0, s2>>>(Q, K);                        // launch 3

    flash_kernel<<<dim3(NSPLIT, BH), 256, FLASH_SMEM>>>(Q, K, V, mask);  // launch 4 (profiled)

    inv_kernel<<<BH, 256, INV_SMEM, s2>>>();
    cudaEventRecord(evInv, s2);

    // s3: fxS (overlaps flash)
    cudaStreamWaitEvent(s3, evPick, 0);
    fxs_kernel<<<dim3(Nv / 64, BH), 256, FXS_SMEM, s3>>>(Q, K);
    cudaEventRecord(evS, s3);

    // main: combine_z (waits inv) -> fxZ (waits fxS)
    cudaStreamWaitEvent(0, evInv, 0);
    combine_z_kernel<<<BH, 256>>>();
    cudaStreamWaitEvent(0, evS, 0);
    fxz_kernel<<<dim3(Nv / 64, BH), 256, FXZ_SMEM>>>(out);
}

// round 17
// speedup vs baseline: 1.0549x; 1.0549x over previous
#include <cuda_runtime.h>
#include <cuda_fp16.h>
#include <float.h>

#define Bv 4
#define Hv 8
#define BH 32
#define Nv 4096
#define Dv 64
#define Mv 64
#define NSPLIT 16
#define CHUNK 256
#define PW 68      // float-plane pitch (words)
#define PH 72      // half-plane pitch (halves)

#define NEG_INF __int_as_float(0xff800000)

typedef unsigned long long u64;

// ---- packed f32x2 helpers (u_kernel) ----
__device__ __forceinline__ u64 ffma2(u64 a, u64 b, u64 c) {
    u64 d;
    asm("fma.rn.f32x2 %0, %1, %2, %3;" : "=l"(d) : "l"(a), "l"(b), "l"(c));
    return d;
}
__device__ __forceinline__ float pairsum(u64 v) {
    unsigned lo, hi;
    asm("mov.b64 {%0, %1}, %2;" : "=r"(lo), "=r"(hi) : "l"(v));
    return __uint_as_float(lo) + __uint_as_float(hi);
}

// ---- tf32 mma helpers (inv kernel) ----
__device__ __forceinline__ unsigned cvt_tf32(float x) {
    unsigned u;
    asm("cvt.rna.tf32.f32 %0, %1;" : "=r"(u) : "f"(x));
    return u;
}
__device__ __forceinline__ void split_tf32(float x, unsigned& hi, unsigned& lo) {
    hi = cvt_tf32(x);
    lo = cvt_tf32(x - __uint_as_float(hi));
}
__device__ __forceinline__ void mma8(float c[4], const unsigned a[4], unsigned b0, unsigned b1) {
    asm("mma.sync.aligned.m16n8k8.row.col.f32.tf32.tf32.f32 "
        "{%0,%1,%2,%3},{%4,%5,%6,%7},{%8,%9},{%0,%1,%2,%3};"
        : "+f"(c[0]), "+f"(c[1]), "+f"(c[2]), "+f"(c[3])
        : "r"(a[0]), "r"(a[1]), "r"(a[2]), "r"(a[3]), "r"(b0), "r"(b1));
}
__device__ __forceinline__ void mma3(float c[4], const unsigned ah[4], const unsigned al[4],
                                     unsigned bh0, unsigned bh1, unsigned bl0, unsigned bl1) {
    mma8(c, ah, bh0, bh1);
    mma8(c, ah, bl0, bl1);
    mma8(c, al, bh0, bh1);
}
// ---- fp16 mma (m16n8k16) ----
__device__ __forceinline__ void mma16(float c[4], const unsigned a[4], unsigned b0, unsigned b1) {
    asm("mma.sync.aligned.m16n8k16.row.col.f32.f16.f16.f32 "
        "{%0,%1,%2,%3},{%4,%5,%6,%7},{%8,%9},{%0,%1,%2,%3};"
        : "+f"(c[0]), "+f"(c[1]), "+f"(c[2]), "+f"(c[3])
        : "r"(a[0]), "r"(a[1]), "r"(a[2]), "r"(a[3]), "r"(b0), "r"(b1));
}

// half split helpers
__device__ __forceinline__ void hsplit(float x, __half& h, __half& l) {
    h = __float2half_rn(x);
    l = __float2half_rn(x - __half2float(h));
}

// fp16 1-plane GEMM: A half plane, B single half plane
__device__ __forceinline__ void gemm16a(const __half* __restrict__ Ah,
                                        const __half* __restrict__ Bh,
                                        float c[4][4], int wn, int r0, int r1, int qr, int qc) {
    #pragma unroll
    for (int k16 = 0; k16 < 4; k16++) {
        int kb = k16 * 16 + 2 * qc;
        unsigned a[4];
        a[0] = *(const unsigned*)&Ah[r0 * PH + kb];
        a[1] = *(const unsigned*)&Ah[r1 * PH + kb];
        a[2] = *(const unsigned*)&Ah[r0 * PH + kb + 8];
        a[3] = *(const unsigned*)&Ah[r1 * PH + kb + 8];
        #pragma unroll
        for (int nt = 0; nt < 4; nt++) {
            int bn = wn * 32 + nt * 8 + qr;
            unsigned bh0 = *(const unsigned*)&Bh[bn * PH + kb];
            unsigned bh1 = *(const unsigned*)&Bh[bn * PH + kb + 8];
            mma16(c[nt], a, bh0, bh1);
        }
    }
}

// fp16 2-term GEMM: A half plane, B hi/lo half planes
__device__ __forceinline__ void gemm16b(const __half* __restrict__ Ah,
                                        const __half* __restrict__ Bh,
                                        const __half* __restrict__ Bl,
                                        float c[4][4], int wn, int r0, int r1, int qr, int qc) {
    #pragma unroll
    for (int k16 = 0; k16 < 4; k16++) {
        int kb = k16 * 16 + 2 * qc;
        unsigned a[4];
        a[0] = *(const unsigned*)&Ah[r0 * PH + kb];
        a[1] = *(const unsigned*)&Ah[r1 * PH + kb];
        a[2] = *(const unsigned*)&Ah[r0 * PH + kb + 8];
        a[3] = *(const unsigned*)&Ah[r1 * PH + kb + 8];
        #pragma unroll
        for (int nt = 0; nt < 4; nt++) {
            int bn = wn * 32 + nt * 8 + qr;
            unsigned bh0 = *(const unsigned*)&Bh[bn * PH + kb];
            unsigned bh1 = *(const unsigned*)&Bh[bn * PH + kb + 8];
            unsigned bl0 = *(const unsigned*)&Bl[bn * PH + kb];
            unsigned bl1 = *(const unsigned*)&Bl[bn * PH + kb + 8];
            mma16(c[nt], a, bh0, bh1);
            mma16(c[nt], a, bl0, bl1);
        }
    }
}

// fp16 3-term GEMM: A hi/lo, B hi/lo (scores path, ~22-bit accuracy)
__device__ __forceinline__ void gemm16_3(const __half* __restrict__ Ah, const __half* __restrict__ Al,
                                         const __half* __restrict__ Bh, const __half* __restrict__ Bl,
                                         float c[4][4], int wn, int r0, int r1, int qr, int qc) {
    #pragma unroll
    for (int k16 = 0; k16 < 4; k16++) {
        int kb = k16 * 16 + 2 * qc;
        unsigned ah[4], al[4];
        ah[0] = *(const unsigned*)&Ah[r0 * PH + kb];
        ah[1] = *(const unsigned*)&Ah[r1 * PH + kb];
        ah[2] = *(const unsigned*)&Ah[r0 * PH + kb + 8];
        ah[3] = *(const unsigned*)&Ah[r1 * PH + kb + 8];
        al[0] = *(const unsigned*)&Al[r0 * PH + kb];
        al[1] = *(const unsigned*)&Al[r1 * PH + kb];
        al[2] = *(const unsigned*)&Al[r0 * PH + kb + 8];
        al[3] = *(const unsigned*)&Al[r1 * PH + kb + 8];
        #pragma unroll
        for (int nt = 0; nt < 4; nt++) {
            int bn = wn * 32 + nt * 8 + qr;
            unsigned bh0 = *(const unsigned*)&Bh[bn * PH + kb];
            unsigned bh1 = *(const unsigned*)&Bh[bn * PH + kb + 8];
            unsigned bl0 = *(const unsigned*)&Bl[bn * PH + kb];
            unsigned bl1 = *(const unsigned*)&Bl[bn * PH + kb + 8];
            mma16(c[nt], ah, bh0, bh1);
            mma16(c[nt], ah, bl0, bl1);
            mma16(c[nt], al, bh0, bh1);
        }
    }
}

// ---------------- scratch ----------------
__device__ float  g_rs[2 * BH * Nv];
__device__ int    g_cidx[BH * Mv];
__device__ int    g_ridx[BH * Mv];
__device__ float  g_u[BH * Mv * Mv];
__device__ float  g_Vinv[BH * Mv * Mv];
__device__ float  g_Yp[(size_t)BH * NSPLIT * Mv * Dv];
__device__ float  g_mx[BH * NSPLIT * Mv];
__device__ float  g_sm[BH * NSPLIT * Mv];
__device__ float  g_Y[BH * Mv * Dv];
__device__ float  g_Zt[BH * Mv * Dv];
__device__ __half g_Ph[(size_t)BH * Nv * Mv];
__device__ unsigned int g_gmax;

// ---------------- row sums (wide) + gmax reset ----------------
__global__ __launch_bounds__(256) void rowsum_kernel(const float* __restrict__ Kp,
                                                     const float* __restrict__ Qp,
                                                     const int* __restrict__ mask) {
    int bh = blockIdx.x, y = blockIdx.y;
    int b = bh / Hv;
    const float* T = (y == 0) ? Kp : Qp;
    const float* Tb = T + (size_t)bh * Nv * Dv;
    float* outs = g_rs + (y * BH + bh) * Nv;
    int base = blockIdx.z * 512;

    if (bh == 0 && y == 0 && blockIdx.z == 0 && threadIdx.x == 0) g_gmax = 0u;

    int hw = threadIdx.x >> 4, l16 = threadIdx.x & 15;
    for (int i = hw; i < 512; i += 16) {
        int r = base + i;
        float4 v4 = *(const float4*)(Tb + (size_t)r * Dv + l16 * 4);
        float v = (v4.x + v4.y) + (v4.z + v4.w);
        #pragma unroll
        for (int o = 1; o <= 8; o <<= 1) v += __shfl_xor_sync(0xffffffffu, v, o);
        if (l16 == 0) {
            bool bad = (r == 0) || (mask[b * Nv + r] != 0);
            outs[r] = bad ? -FLT_MAX : v;
        }
    }
}

// ---------------- top-k pick ----------------
__global__ __launch_bounds__(256) void pick_kernel() {
    int bh = blockIdx.x;
    int* outIdx = (blockIdx.y == 0) ? g_cidx : g_ridx;
    const float* ins = g_rs + (blockIdx.y * BH + bh) * Nv;

    __shared__ float s[Nv];
    __shared__ float cmax[16];
    __shared__ int   cidx[16];
    __shared__ int   picked[Mv];

    int tid = threadIdx.x;
    int warp = tid >> 5, lane = tid & 31;

    for (int i = tid; i < Nv / 4; i += 256)
        *(float4*)&s[i * 4] = *(const float4*)(ins + i * 4);
    __syncthreads();

    for (int c = warp; c < 16; c += 8) {
        float bv = -FLT_MAX; int bi = Nv;
        #pragma unroll
        for (int t = 0; t < 8; t++) {
            int idx = c * 256 + lane + 32 * t;
            float v = s[idx];
            if (v > bv || (v == bv && idx < bi)) { bv = v; bi = idx; }
        }
        #pragma unroll
        for (int o = 16; o; o >>= 1) {
            float ov = __shfl_xor_sync(0xffffffffu, bv, o);
            int   oi = __shfl_xor_sync(0xffffffffu, bi, o);
            if (ov > bv || (ov == bv && oi < bi)) { bv = ov; bi = oi; }
        }
        if (lane == 0) { cmax[c] = bv; cidx[c] = bi; }
    }
    __syncthreads();

    if (warp == 0) {
        for (int it = 0; it < Mv - 1; ++it) {
            float bv = (lane < 16) ? cmax[lane] : -FLT_MAX;
            int   bi = (lane < 16) ? cidx[lane] : Nv;
            #pragma unroll
            for (int o = 16; o; o >>= 1) {
                float ov = __shfl_xor_sync(0xffffffffu, bv, o);
                int   oi = __shfl_xor_sync(0xffffffffu, bi, o);
                if (ov > bv || (ov == bv && oi < bi)) { bv = ov; bi = oi; }
            }
            int gidx = __shfl_sync(0xffffffffu, bi, 0);
            if (lane == 0) { picked[it] = gidx; s[gidx] = -FLT_MAX; }
            __syncwarp();
            int c = gidx >> 8;
            float nv = -FLT_MAX; int ni = Nv;
            #pragma unroll
            for (int t = 0; t < 8; t++) {
                int idx = c * 256 + lane + 32 * t;
                float v = s[idx];
                if (v > nv || (v == nv && idx < ni)) { nv = v; ni = idx; }
            }
            #pragma unroll
            for (int o = 16; o; o >>= 1) {
                float ov = __shfl_xor_sync(0xffffffffu, nv, o);
                int   oi = __shfl_xor_sync(0xffffffffu, ni, o);
                if (ov > nv || (ov == nv && oi < ni)) { nv = ov; ni = oi; }
            }
            if (lane == 0) { cmax[c] = nv; cidx[c] = ni; }
            __syncwarp();
        }
        if (lane == 0) picked[Mv - 1] = 0;
    }
    __syncthreads();

    if (tid < Mv) {
        int key = picked[tid];
        int rank = 0;
        #pragma unroll 16
        for (int j = 0; j < Mv; j++) rank += (picked[j] < key);
        outIdx[bh * Mv + rank] = key;
    }
}

// ---------------- u = softmax(Qs[ridx] @ nc^T) + global colsum-max ----------
__global__ __launch_bounds__(256) void u_kernel(const float* __restrict__ Q,
                                                const float* __restrict__ K) {
    int bh = blockIdx.x;
    __shared__ float Kc[64 * PW];
    __shared__ float Qr[64 * PW];
    __shared__ float colsum[64];
    __shared__ int ci_s[64], ri_s[64];

    const float* Kb = K + (size_t)bh * Nv * Dv;
    const float* Qb = Q + (size_t)bh * Nv * Dv;
    int tid = threadIdx.x;
    if (tid < 64) { ci_s[tid] = g_cidx[bh * Mv + tid]; ri_s[tid] = g_ridx[bh * Mv + tid]; }
    __syncthreads();

    for (int idx = tid; idx < 64 * 16; idx += 256) {
        int r = idx >> 4, c4 = (idx & 15) * 4;
        float4 q4 = *(const float4*)(Qb + (size_t)ri_s[r] * Dv + c4);
        q4.x *= 0.125f; q4.y *= 0.125f; q4.z *= 0.125f; q4.w *= 0.125f;
        *(float4*)&Qr[r * PW + c4] = q4;
        *(float4*)&Kc[r * PW + c4] = *(const float4*)(Kb + (size_t)ci_s[r] * Dv + c4);
    }
    __syncthreads();

    int tx = tid & 15, ty = tid >> 4;
    u64 sc2[4][4];
    #pragma unroll
    for (int i = 0; i < 4; i++)
        #pragma unroll
        for (int j = 0; j < 4; j++) sc2[i][j] = 0ull;
    #pragma unroll 4
    for (int k4 = 0; k4 < 16; k4++) {
        ulonglong2 a2[4], b2[4];
        #pragma unroll
        for (int i = 0; i < 4; i++) a2[i] = *(const ulonglong2*)&Qr[(ty * 4 + i) * PW + k4 * 4];
        #pragma unroll
        for (int j = 0; j < 4; j++) b2[j] = *(const ulonglong2*)&Kc[(tx + 16 * j) * PW + k4 * 4];
        #pragma unroll
        for (int i = 0; i < 4; i++)
            #pragma unroll
            for (int j = 0; j < 4; j++) {
                sc2[i][j] = ffma2(a2[i].x, b2[j].x, sc2[i][j]);
                sc2[i][j] = ffma2(a2[i].y, b2[j].y, sc2[i][j]);
            }
    }
    __syncthreads();

    #pragma unroll
    for (int i = 0; i < 4; i++) {
        float sv[4];
        #pragma unroll
        for (int j = 0; j < 4; j++) sv[j] = pairsum(sc2[i][j]);
        float mx = fmaxf(fmaxf(sv[0], sv[1]), fmaxf(sv[2], sv[3]));
        #pragma unroll
        for (int o = 8; o; o >>= 1) mx = fmaxf(mx, __shfl_xor_sync(0xffffffffu, mx, o));
        float e[4], sm = 0.f;
        #pragma unroll
        for (int j = 0; j < 4; j++) { e[j] = __expf(sv[j] - mx); sm += e[j]; }
        #pragma unroll
        for (int o = 8; o; o >>= 1) sm += __shfl_xor_sync(0xffffffffu, sm, o);
        float inv = 1.f / sm;
        int row = ty * 4 + i;
        #pragma unroll
        for (int j = 0; j < 4; j++) {
            float p = e[j] * inv;
            Qr[row * PW + tx + 16 * j] = p;
            g_u[(bh * 64 + row) * 64 + tx + 16 * j] = p;
        }
    }
    __syncthreads();
    if (tid < 64) {
        float s = 0.f;
        #pragma unroll 8
        for (int i = 0; i < 64; i++) s += Qr[i * PW + tid];
        colsum[tid] = s;
    }
    __syncthreads();
    if (tid == 0) {
        float mx = colsum[0];
        for (int j = 1; j < 64; j++) mx = fmaxf(mx, colsum[j]);
        atomicMax(&g_gmax, __float_as_uint(mx));
    }
}

// ---------------- mm64v ----------------
__device__ __forceinline__ void mm64v(const float* __restrict__ A,
                                      const float* __restrict__ Bm,
                                      float acc[4][4], int tx, int ty) {
    #pragma unroll
    for (int i = 0; i < 4; i++)
        #pragma unroll
        for (int j = 0; j < 4; j++) acc[i][j] = 0.f;
    #pragma unroll 2
    for (int k4 = 0; k4 < 16; k4++) {
        float4 a[4];
        #pragma unroll
        for (int i = 0; i < 4; i++) a[i] = *(const float4*)&A[(ty * 4 + i) * 64 + k4 * 4];
        #pragma unroll
        for (int kk = 0; kk < 4; kk++) {
            float4 bv = *(const float4*)&Bm[(k4 * 4 + kk) * 64 + tx * 4];
            float av[4];
            av[0] = (kk == 0) ? a[0].x : (kk == 1) ? a[0].y : (kk == 2) ? a[0].z : a[0].w;
            av[1] = (kk == 0) ? a[1].x : (kk == 1) ? a[1].y : (kk == 2) ? a[1].z : a[1].w;
            av[2] = (kk == 0) ? a[2].x : (kk == 1) ? a[2].y : (kk == 2) ? a[2].z : a[2].w;
            av[3] = (kk == 0) ? a[3].x : (kk == 1) ? a[3].y : (kk == 2) ? a[3].z : a[3].w;
            #pragma unroll
            for (int i = 0; i < 4; i++) {
                acc[i][0] = fmaf(av[i], bv.x, acc[i][0]);
                acc[i][1] = fmaf(av[i], bv.y, acc[i][1]);
                acc[i][2] = fmaf(av[i], bv.z, acc[i][2]);
                acc[i][3] = fmaf(av[i], bv.w, acc[i][3]);
            }
        }
    }
}

// ---------------- Newton-Schulz inverse (3xTF32, inline split) ----------------
__device__ __forceinline__ void gemm3(const float* __restrict__ Arow, const float* __restrict__ Bt,
                                      float c[4][4], int wn, int r0, int r1, int qr, int qc) {
    #pragma unroll
    for (int nt = 0; nt < 4; nt++) { c[nt][0] = c[nt][1] = c[nt][2] = c[nt][3] = 0.f; }
    #pragma unroll
    for (int k8 = 0; k8 < 8; k8++) {
        int kb = k8 * 8;
        unsigned ah[4], al[4];
        split_tf32(Arow[r0 * PW + kb + qc],     ah[0], al[0]);
        split_tf32(Arow[r1 * PW + kb + qc],     ah[1], al[1]);
        split_tf32(Arow[r0 * PW + kb + 4 + qc], ah[2], al[2]);
        split_tf32(Arow[r1 * PW + kb + 4 + qc], ah[3], al[3]);
        #pragma unroll
        for (int nt = 0; nt < 4; nt++) {
            int bn = wn * 32 + nt * 8 + qr;
            unsigned bh0, bl0, bh1, bl1;
            split_tf32(Bt[bn * PW + kb + qc],     bh0, bl0);
            split_tf32(Bt[bn * PW + kb + 4 + qc], bh1, bl1);
            mma3(c[nt], ah, al, bh0, bh1, bl0, bl1);
        }
    }
}

extern __shared__ float invsm[];
__global__ __launch_bounds__(256) void inv_kernel() {
    float* Us  = invsm;
    float* Vr  = Us  + 64 * PW;
    float* Vt  = Vr  + 64 * PW;
    float* Ar  = Vt  + 64 * PW;
    float* At  = Ar  + 64 * PW;
    float* Tt  = At  + 64 * PW;
    float* T2t = Tt  + 64 * PW;

    int bh = blockIdx.x, tid = threadIdx.x;
    int wid = tid >> 5, lane = tid & 31;
    int wm = wid & 3, wn = wid >> 2;
    int qr = lane >> 2, qc = lane & 3;
    int r0 = wm * 16 + qr, r1 = r0 + 8;

    const float* Ug = g_u + (size_t)bh * 4096;
    float ginv = 1.f / __uint_as_float(g_gmax);

    for (int idx = tid; idx < 1024; idx += 256) {
        int r = idx >> 4, c4 = (idx & 15) * 4;
        float4 u4 = *(const float4*)(Ug + r * 64 + c4);
        *(float4*)&Us[r * PW + c4] = u4;
        float4 s4 = make_float4(u4.x * ginv, u4.y * ginv, u4.z * ginv, u4.w * ginv);
        *(float4*)&Vt[r * PW + c4] = s4;
        Vr[(c4 + 0) * PW + r] = s4.x;
        Vr[(c4 + 1) * PW + r] = s4.y;
        Vr[(c4 + 2) * PW + r] = s4.z;
        Vr[(c4 + 3) * PW + r] = s4.w;
    }
    __syncthreads();

    float c1[4][4], cw[4][4];
    for (int it = 0; it < 6; it++) {
        gemm3(Us, Vt, c1, wn, r0, r1, qr, qc);
        #pragma unroll
        for (int nt = 0; nt < 4; nt++) {
            int c0 = wn * 32 + nt * 8 + 2 * qc;
            Ar[r0 * PW + c0] = c1[nt][0]; Ar[r0 * PW + c0 + 1] = c1[nt][1];
            Ar[r1 * PW + c0] = c1[nt][2]; Ar[r1 * PW + c0 + 1] = c1[nt][3];
            At[c0 * PW + r0] = c1[nt][0]; At[(c0 + 1) * PW + r0] = c1[nt][1];
            At[c0 * PW + r1] = c1[nt][2]; At[(c0 + 1) * PW + r1] = c1[nt][3];
        }
        __syncthreads();

        gemm3(Ar, At, cw, wn, r0, r1, qr, qc);
        #pragma unroll
        for (int nt = 0; nt < 4; nt++) {
            int c0 = wn * 32 + nt * 8 + 2 * qc;
            Tt[c0 * PW + r0]       = 7.f * c1[nt][0] - cw[nt][0];
            Tt[(c0 + 1) * PW + r0] = 7.f * c1[nt][1] - cw[nt][1];
            Tt[c0 * PW + r1]       = 7.f * c1[nt][2] - cw[nt][2];
            Tt[(c0 + 1) * PW + r1] = 7.f * c1[nt][3] - cw[nt][3];
        }
        __syncthreads();

        gemm3(Ar, Tt, cw, wn, r0, r1, qr, qc);
        #pragma unroll
        for (int nt = 0; nt < 4; nt++) {
            int c0 = wn * 32 + nt * 8 + 2 * qc;
            T2t[c0 * PW + r0]       = 15.f * c1[nt][0] - cw[nt][0];
            T2t[(c0 + 1) * PW + r0] = 15.f * c1[nt][1] - cw[nt][1];
            T2t[c0 * PW + r1]       = 15.f * c1[nt][2] - cw[nt][2];
            T2t[(c0 + 1) * PW + r1] = 15.f * c1[nt][3] - cw[nt][3];
        }
        __syncthreads();

        gemm3(Vr, T2t, cw, wn, r0, r1, qr, qc);
        __syncthreads();
        #pragma unroll
        for (int nt = 0; nt < 4; nt++) {
            int c0 = wn * 32 + nt * 8 + 2 * qc;
            float v00 = Vr[r0 * PW + c0], v01 = Vr[r0 * PW + c0 + 1];
            float v10 = Vr[r1 * PW + c0], v11 = Vr[r1 * PW + c0 + 1];
            float n00 = 0.25f * (13.f * v00 - cw[nt][0]);
            float n01 = 0.25f * (13.f * v01 - cw[nt][1]);
            float n10 = 0.25f * (13.f * v10 - cw[nt][2]);
            float n11 = 0.25f * (13.f * v11 - cw[nt][3]);
            Vr[r0 * PW + c0] = n00; Vr[r0 * PW + c0 + 1] = n01;
            Vr[r1 * PW + c0] = n10; Vr[r1 * PW + c0 + 1] = n11;
            Vt[c0 * PW + r0] = n00; Vt[(c0 + 1) * PW + r0] = n01;
            Vt[c0 * PW + r1] = n10; Vt[(c0 + 1) * PW + r1] = n11;
        }
        __syncthreads();
    }

    for (int idx = tid; idx < 1024; idx += 256) {
        int r = idx >> 4, c4 = (idx & 15) * 4;
        *(float4*)(g_Vinv + (size_t)bh * 4096 + r * 64 + c4) = *(float4*)&Vr[r * PW + c4];
    }
}

// ---------------- flash: S via fp16 3-term, PV via fp16 1-plane V ----------
extern __shared__ float fsmem[];
__global__ __launch_bounds__(256, 4) void flash_kernel(const float* __restrict__ Q,
                                                       const float* __restrict__ K,
                                                       const float* __restrict__ V,
                                                       const int* __restrict__ mask) {
    __half* Qh = (__half*)fsmem;            // nr hi [m][d]
    __half* Ql = Qh + 64 * PH;              // nr lo
    __half* Ph = Ql + 64 * PH;              // P [m][n]
    __half* Bh = Ph + 64 * PH;              // K hi [n][d], then V hi [d][n]
    __half* Bl = Bh + 64 * PH;              // K lo (scores only)
    __shared__ float rmaxp[2][64];
    __shared__ float rsump[2][64];
    __shared__ int msk[64];
    __shared__ int ri_s[64];

    int bh = blockIdx.y, sp = blockIdx.x;
    int b = bh / Hv;
    const float* Qb = Q + (size_t)bh * Nv * Dv;
    const float* Kb = K + (size_t)bh * Nv * Dv;
    const float* Vb = V + (size_t)bh * Nv * Dv;

    int tid = threadIdx.x;
    int wid = tid >> 5, lane = tid & 31;
    int wm = wid & 3, wn = wid >> 2;
    int qr = lane >> 2, qc = lane & 3;
    int r0 = wm * 16 + qr, r1 = r0 + 8;

    if (tid < 64) ri_s[tid] = g_ridx[bh * Mv + tid];
    __syncthreads();
    for (int idx = tid; idx < 64 * 16; idx += 256) {
        int r = idx >> 4, c4 = (idx & 15) * 4;
        float4 q4 = *(const float4*)(Qb + (size_t)ri_s[r] * Dv + c4);
        __half h, l;
        hsplit(q4.x * 0.125f, h, l); Qh[r * PH + c4 + 0] = h; Ql[r * PH + c4 + 0] = l;
        hsplit(q4.y * 0.125f, h, l); Qh[r * PH + c4 + 1] = h; Ql[r * PH + c4 + 1] = l;
        hsplit(q4.z * 0.125f, h, l); Qh[r * PH + c4 + 2] = h; Ql[r * PH + c4 + 2] = l;
        hsplit(q4.w * 0.125f, h, l); Qh[r * PH + c4 + 3] = h; Ql[r * PH + c4 + 3] = l;
    }

    float o[4][4];
    #pragma unroll
    for (int nt = 0; nt < 4; nt++)
        #pragma unroll
        for (int j = 0; j < 4; j++) o[nt][j] = 0.f;
    float m0 = NEG_INF, m1 = NEG_INF, l0 = 0.f, l1 = 0.f;

    int base0 = sp * CHUNK;
    for (int t = 0; t < CHUNK / 64; t++) {
        int base = base0 + t * 64;
        __syncthreads();                       // B planes + Ph free; Q ready on t=0
        for (int idx = tid; idx < 64 * 16; idx += 256) {
            int r = idx >> 4, c4 = (idx & 15) * 4;
            float4 k4 = *(const float4*)(Kb + (size_t)(base + r) * Dv + c4);
            __half h, l;
            hsplit(k4.x, h, l); Bh[r * PH + c4 + 0] = h; Bl[r * PH + c4 + 0] = l;
            hsplit(k4.y, h, l); Bh[r * PH + c4 + 1] = h; Bl[r * PH + c4 + 1] = l;
            hsplit(k4.z, h, l); Bh[r * PH + c4 + 2] = h; Bl[r * PH + c4 + 2] = l;
            hsplit(k4.w, h, l); Bh[r * PH + c4 + 3] = h; Bl[r * PH + c4 + 3] = l;
        }
        if (tid < 64) msk[tid] = mask[b * Nv + base + tid];
        __syncthreads();

        // ---- S = nr @ K^T (fp16 3-term) ----
        float s[4][4];
        #pragma unroll
        for (int nt = 0; nt < 4; nt++)
            #pragma unroll
            for (int j = 0; j < 4; j++) s[nt][j] = 0.f;
        gemm16_3(Qh, Ql, Bh, Bl, s, wn, r0, r1, qr, qc);

        // ---- mask + row max ----
        float rmA = NEG_INF, rmB = NEG_INF;
        #pragma unroll
        for (int nt = 0; nt < 4; nt++) {
            int c0 = wn * 32 + nt * 8 + 2 * qc, c1c = c0 + 1;
            if (!msk[c0])  { s[nt][0] = NEG_INF; s[nt][2] = NEG_INF; }
            if (!msk[c1c]) { s[nt][1] = NEG_INF; s[nt][3] = NEG_INF; }
            rmA = fmaxf(rmA, fmaxf(s[nt][0], s[nt][1]));
            rmB = fmaxf(rmB, fmaxf(s[nt][2], s[nt][3]));
        }
        #pragma unroll
        for (int o2 = 1; o2 <= 2; o2 <<= 1) {
            rmA = fmaxf(rmA, __shfl_xor_sync(0xffffffffu, rmA, o2));
            rmB = fmaxf(rmB, __shfl_xor_sync(0xffffffffu, rmB, o2));
        }
        if (qc == 0) { rmaxp[wn][r0] = rmA; rmaxp[wn][r1] = rmB; }
        __syncthreads();                       // S reads of K planes done

        // ---- V tile -> Bh plane only (transposed, fp16 hi) + online softmax ----
        for (int idx = tid; idx < 64 * 16; idx += 256) {
            int r = idx & 63, c4 = (idx >> 6) * 4;
            float4 v = *(const float4*)(Vb + (size_t)(base + r) * Dv + c4);
            Bh[(c4 + 0) * PH + r] = __float2half_rn(v.x);
            Bh[(c4 + 1) * PH + r] = __float2half_rn(v.y);
            Bh[(c4 + 2) * PH + r] = __float2half_rn(v.z);
            Bh[(c4 + 3) * PH + r] = __float2half_rn(v.w);
        }
        float tmxA = fmaxf(rmaxp[0][r0], rmaxp[1][r0]);
        float tmxB = fmaxf(rmaxp[0][r1], rmaxp[1][r1]);
        float nmA = fmaxf(m0, tmxA), mcA = fmaxf(nmA, -1e30f);
        float nmB = fmaxf(m1, tmxB), mcB = fmaxf(nmB, -1e30f);
        float alA = __expf(m0 - mcA), alB = __expf(m1 - mcB);
        m0 = nmA; m1 = nmB;
        float tsA = 0.f, tsB = 0.f;
        #pragma unroll
        for (int nt = 0; nt < 4; nt++) {
            int c0 = wn * 32 + nt * 8 + 2 * qc;
            float p00 = __expf(s[nt][0] - mcA), p01 = __expf(s[nt][1] - mcA);
            float p10 = __expf(s[nt][2] - mcB), p11 = __expf(s[nt][3] - mcB);
            tsA += p00 + p01; tsB += p10 + p11;
            *(half2*)&Ph[r0 * PH + c0] = __floats2half2_rn(p00, p01);
            *(half2*)&Ph[r1 * PH + c0] = __floats2half2_rn(p10, p11);
        }
        #pragma unroll
        for (int o2 = 1; o2 <= 2; o2 <<= 1) {
            tsA += __shfl_xor_sync(0xffffffffu, tsA, o2);
            tsB += __shfl_xor_sync(0xffffffffu, tsB, o2);
        }
        l0 = l0 * alA + tsA;
        l1 = l1 * alB + tsB;
        #pragma unroll
        for (int nt = 0; nt < 4; nt++) {
            o[nt][0] *= alA; o[nt][1] *= alA;
            o[nt][2] *= alB; o[nt][3] *= alB;
        }
        __syncthreads();                       // P + V plane ready

        // ---- O += P @ V (fp16, single V plane) ----
        gemm16a(Ph, Bh, o, wn, r0, r1, qr, qc);
    }

    if (qc == 0) { rsump[wn][r0] = l0; rsump[wn][r1] = l1; }
    int idxbase = (bh * NSPLIT + sp) * 64;
    if (wn == 0 && qc == 0) {
        g_mx[idxbase + r0] = m0;
        g_mx[idxbase + r1] = m1;
    }
    __syncthreads();
    if (tid < 64) g_sm[idxbase + tid] = rsump[0][tid] + rsump[1][tid];
    #pragma unroll
    for (int nt = 0; nt < 4; nt++) {
        int c0 = wn * 32 + nt * 8 + 2 * qc;
        *(float2*)&g_Yp[((size_t)idxbase + r0) * 64 + c0] = make_float2(o[nt][0], o[nt][1]);
        *(float2*)&g_Yp[((size_t)idxbase + r1) * 64 + c0] = make_float2(o[nt][2], o[nt][3]);
    }
}

// ---------------- combine split partials into Y (wide) ----------------
__global__ __launch_bounds__(256) void combine_kernel() {
    int bh = blockIdx.x, tid = threadIdx.x;
    int m = blockIdx.y * 16 + (tid >> 4);
    int dq = (tid & 15) * 4;

    float mx = NEG_INF;
    #pragma unroll
    for (int s = 0; s < NSPLIT; s++)
        mx = fmaxf(mx, g_mx[(bh * NSPLIT + s) * 64 + m]);
    float mc = fmaxf(mx, -1e30f);
    float tot = 0.f;
    float4 acc = make_float4(0.f, 0.f, 0.f, 0.f);
    #pragma unroll 4
    for (int s = 0; s < NSPLIT; s++) {
        float w = __expf(g_mx[(bh * NSPLIT + s) * 64 + m] - mc);
        tot += w * g_sm[(bh * NSPLIT + s) * 64 + m];
        float4 yp = *(const float4*)(g_Yp + (((size_t)(bh * NSPLIT + s) * 64) + m) * 64 + dq);
        acc.x += w * yp.x; acc.y += w * yp.y; acc.z += w * yp.z; acc.w += w * yp.w;
    }
    float inv = 1.f / tot;
    *(float4*)(g_Y + ((size_t)bh * 64 + m) * 64 + dq) =
        make_float4(acc.x * inv, acc.y * inv, acc.z * inv, acc.w * inv);
}

// ---------------- Zt = (Vinv @ Y)^T ----------------
__global__ __launch_bounds__(256) void z_kernel() {
    __shared__ float Vv[4096];
    __shared__ float Ys[4096];
    int bh = blockIdx.x, tid = threadIdx.x;
    int tx = tid & 15, ty = tid >> 4;
    for (int i = tid; i < 4096; i += 256) {
        Vv[i] = g_Vinv[(size_t)bh * 4096 + i];
        Ys[i] = g_Y[(size_t)bh * 4096 + i];
    }
    __syncthreads();
    float acc[4][4];
    mm64v(Vv, Ys, acc, tx, ty);
    #pragma unroll
    for (int i = 0; i < 4; i++)
        #pragma unroll
        for (int j = 0; j < 4; j++)
            g_Zt[(size_t)bh * 4096 + (tx * 4 + j) * 64 + ty * 4 + i] = acc[i][j];
}

// ---------------- fxS: P = softmax(Qs @ nc^T) (fp16 3-term scores) -> g_Ph ----
extern __shared__ float xssm[];
__global__ __launch_bounds__(256, 4) void fxs_kernel(const float* __restrict__ Q,
                                                     const float* __restrict__ K) {
    __half* Qh = (__half*)xssm;            // [n][d] hi
    __half* Ql = Qh + 64 * PH;             // lo
    __half* Bh = Ql + 64 * PH;             // nc hi
    __half* Bl = Bh + 64 * PH;             // nc lo
    __shared__ float rmaxp[2][64];
    __shared__ float rsump[2][64];
    __shared__ int ci_s[64];

    int bh = blockIdx.y; int n0 = blockIdx.x * 64;
    const float* Kb = K + (size_t)bh * Nv * Dv;
    const float* Qb = Q + (size_t)bh * Nv * Dv;
    int tid = threadIdx.x;
    int wid = tid >> 5, lane = tid & 31;
    int wm = wid & 3, wn = wid >> 2;
    int qr = lane >> 2, qc = lane & 3;
    int r0 = wm * 16 + qr, r1 = r0 + 8;

    if (tid < 64) ci_s[tid] = g_cidx[bh * Mv + tid];
    __syncthreads();

    for (int idx = tid; idx < 64 * 16; idx += 256) {
        int r = idx >> 4, c4 = (idx & 15) * 4;
        float4 q4 = *(const float4*)(Qb + (size_t)(n0 + r) * Dv + c4);
        __half h, l;
        hsplit(q4.x * 0.125f, h, l); Qh[r * PH + c4 + 0] = h; Ql[r * PH + c4 + 0] = l;
        hsplit(q4.y * 0.125f, h, l); Qh[r * PH + c4 + 1] = h; Ql[r * PH + c4 + 1] = l;
        hsplit(q4.z * 0.125f, h, l); Qh[r * PH + c4 + 2] = h; Ql[r * PH + c4 + 2] = l;
        hsplit(q4.w * 0.125f, h, l); Qh[r * PH + c4 + 3] = h; Ql[r * PH + c4 + 3] = l;
        float4 n4 = *(const float4*)(Kb + (size_t)ci_s[r] * Dv + c4);
        hsplit(n4.x, h, l); Bh[r * PH + c4 + 0] = h; Bl[r * PH + c4 + 0] = l;
        hsplit(n4.y, h, l); Bh[r * PH + c4 + 1] = h; Bl[r * PH + c4 + 1] = l;
        hsplit(n4.z, h, l); Bh[r * PH + c4 + 2] = h; Bl[r * PH + c4 + 2] = l;
        hsplit(n4.w, h, l); Bh[r * PH + c4 + 3] = h; Bl[r * PH + c4 + 3] = l;
    }
    __syncthreads();

    float s[4][4];
    #pragma unroll
    for (int nt = 0; nt < 4; nt++)
        #pragma unroll
        for (int j = 0; j < 4; j++) s[nt][j] = 0.f;
    gemm16_3(Qh, Ql, Bh, Bl, s, wn, r0, r1, qr, qc);

    float rmA = NEG_INF, rmB = NEG_INF;
    #pragma unroll
    for (int nt = 0; nt < 4; nt++) {
        rmA = fmaxf(rmA, fmaxf(s[nt][0], s[nt][1]));
        rmB = fmaxf(rmB, fmaxf(s[nt][2], s[nt][3]));
    }
    #pragma unroll
    for (int o2 = 1; o2 <= 2; o2 <<= 1) {
        rmA = fmaxf(rmA, __shfl_xor_sync(0xffffffffu, rmA, o2));
        rmB = fmaxf(rmB, __shfl_xor_sync(0xffffffffu, rmB, o2));
    }
    if (qc == 0) { rmaxp[wn][r0] = rmA; rmaxp[wn][r1] = rmB; }
    __syncthreads();

    float mcA = fmaxf(rmaxp[0][r0], rmaxp[1][r0]);
    float mcB = fmaxf(rmaxp[0][r1], rmaxp[1][r1]);
    float p[4][4];
    float tsA = 0.f, tsB = 0.f;
    #pragma unroll
    for (int nt = 0; nt < 4; nt++) {
        p[nt][0] = __expf(s[nt][0] - mcA); p[nt][1] = __expf(s[nt][1] - mcA);
        p[nt][2] = __expf(s[nt][2] - mcB); p[nt][3] = __expf(s[nt][3] - mcB);
        tsA += p[nt][0] + p[nt][1]; tsB += p[nt][2] + p[nt][3];
    }
    #pragma unroll
    for (int o2 = 1; o2 <= 2; o2 <<= 1) {
        tsA += __shfl_xor_sync(0xffffffffu, tsA, o2);
        tsB += __shfl_xor_sync(0xffffffffu, tsB, o2);
    }
    if (qc == 0) { rsump[wn][r0] = tsA; rsump[wn][r1] = tsB; }
    __syncthreads();

    float invA = 1.f / (rsump[0][r0] + rsump[1][r0]);
    float invB = 1.f / (rsump[0][r1] + rsump[1][r1]);
    __half* Pg = g_Ph + (size_t)bh * Nv * Mv;
    #pragma unroll
    for (int nt = 0; nt < 4; nt++) {
        int c0 = wn * 32 + nt * 8 + 2 * qc;
        *(half2*)(Pg + (size_t)(n0 + r0) * Mv + c0) = __floats2half2_rn(p[nt][0] * invA, p[nt][1] * invA);
        *(half2*)(Pg + (size_t)(n0 + r1) * Mv + c0) = __floats2half2_rn(p[nt][2] * invB, p[nt][3] * invB);
    }
}

// ---------------- fxZ: X = P @ Z (fp16, Z hi/lo) ----------------
extern __shared__ float xzsm[];
__global__ __launch_bounds__(256, 4) void fxz_kernel(float* __restrict__ out) {
    __half* Pp = (__half*)xzsm;                     // [n][m'] half, pitch PH
    __half* Zh = Pp + 64 * PH;                      // [d][m'] half hi
    __half* Zl = Zh + 64 * PH;                      // [d][m'] half lo

    int bh = blockIdx.y; int n0 = blockIdx.x * 64;
    int tid = threadIdx.x;
    int wid = tid >> 5, lane = tid & 31;
    int wm = wid & 3, wn = wid >> 2;
    int qr = lane >> 2, qc = lane & 3;
    int r0 = wm * 16 + qr, r1 = r0 + 8;

    const __half* Pg = g_Ph + (size_t)bh * Nv * Mv;
    for (int idx = tid; idx < 64 * 8; idx += 256) {
        int r = idx >> 3, c8 = (idx & 7) * 8;
        *(uint4*)&Pp[r * PH + c8] = *(const uint4*)(Pg + (size_t)(n0 + r) * Mv + c8);
    }
    for (int idx = tid; idx < 64 * 16; idx += 256) {
        int r = idx >> 4, c4 = (idx & 15) * 4;
        float4 z4 = *(const float4*)(g_Zt + (size_t)bh * 4096 + r * 64 + c4);
        __half h, l;
        hsplit(z4.x, h, l); Zh[r * PH + c4 + 0] = h; Zl[r * PH + c4 + 0] = l;
        hsplit(z4.y, h, l); Zh[r * PH + c4 + 1] = h; Zl[r * PH + c4 + 1] = l;
        hsplit(z4.z, h, l); Zh[r * PH + c4 + 2] = h; Zl[r * PH + c4 + 2] = l;
        hsplit(z4.w, h, l); Zh[r * PH + c4 + 3] = h; Zl[r * PH + c4 + 3] = l;
    }
    __syncthreads();

    float o[4][4];
    #pragma unroll
    for (int nt = 0; nt < 4; nt++)
        #pragma unroll
        for (int j = 0; j < 4; j++) o[nt][j] = 0.f;
    gemm16b(Pp, Zh, Zl, o, wn, r0, r1, qr, qc);

    #pragma unroll
    for (int nt = 0; nt < 4; nt++) {
        int c0 = wn * 32 + nt * 8 + 2 * qc;
        *(float2*)(out + ((size_t)bh * Nv + n0 + r0) * Dv + c0) = make_float2(o[nt][0], o[nt][1]);
        *(float2*)(out + ((size_t)bh * Nv + n0 + r1) * Dv + c0) = make_float2(o[nt][2], o[nt][3]);
    }
}

// ---------------- launch ----------------
extern "C" void kernel_launch(void* const* d_in, const int* in_sizes, int n_in,
                              void* d_out, int out_size) {
    (void)in_sizes; (void)n_in; (void)out_size;
    const float* Q    = (const float*)d_in[0];
    const float* K    = (const float*)d_in[1];
    const float* V    = (const float*)d_in[2];
    const int*   mask = (const int*)d_in[3];
    float* out = (float*)d_out;

    const int FLASH_SMEM = 5 * 64 * PH * 2;                  // 46080 -> 4 CTAs/SM
    const int FXS_SMEM   = 4 * 64 * PH * 2;                  // 36864
    const int FXZ_SMEM   = 3 * 64 * PH * 2;                  // 27648
    const int INV_SMEM   = 7 * 64 * PW * (int)sizeof(float); // 121856

    static bool init_done = false;
    static cudaStream_t s2, s3;
    static cudaEvent_t evPick, evInv, evS;
    if (!init_done) {
        cudaFuncSetAttribute(flash_kernel, cudaFuncAttributeMaxDynamicSharedMemorySize, FLASH_SMEM);
        cudaFuncSetAttribute(fxs_kernel, cudaFuncAttributeMaxDynamicSharedMemorySize, FXS_SMEM);
        cudaFuncSetAttribute(fxz_kernel, cudaFuncAttributeMaxDynamicSharedMemorySize, FXZ_SMEM);
        cudaFuncSetAttribute(inv_kernel, cudaFuncAttributeMaxDynamicSharedMemorySize, INV_SMEM);
        cudaStreamCreateWithFlags(&s2, cudaStreamNonBlocking);
        cudaStreamCreateWithFlags(&s3, cudaStreamNonBlocking);
        cudaEventCreateWithFlags(&evPick, cudaEventDisableTiming);
        cudaEventCreateWithFlags(&evInv, cudaEventDisableTiming);
        cudaEventCreateWithFlags(&evS, cudaEventDisableTiming);
        init_done = true;
    }

    rowsum_kernel<<<dim3(BH, 2, 8), 256>>>(K, Q, mask);        // launch 1
    pick_kernel<<<dim3(BH, 2), 256>>>();                       // launch 2
    cudaEventRecord(evPick, 0);

    // s2: u -> inv (overlaps flash)
    cudaStreamWaitEvent(s2, evPick, 0);
    u_kernel<<<BH, 256, 0, s2>>>(Q, K);                        // launch 3

    flash_kernel<<<dim3(NSPLIT, BH), 256, FLASH_SMEM>>>(Q, K, V, mask);  // launch 4 (profiled)

    inv_kernel<<<BH, 256, INV_SMEM, s2>>>();
    cudaEventRecord(evInv, s2);

    // s3: fxS (overlaps flash)
    cudaStreamWaitEvent(s3, evPick, 0);
    fxs_kernel<<<dim3(Nv / 64, BH), 256, FXS_SMEM, s3>>>(Q, K);
    cudaEventRecord(evS, s3);

    // main: wide combine (depends only on flash; overlaps inv tail) -> z -> fxZ
    combine_kernel<<<dim3(BH, 4), 256>>>();
    cudaStreamWaitEvent(0, evInv, 0);
    z_kernel<<<BH, 256>>>();
    cudaStreamWaitEvent(0, evS, 0);
    fxz_kernel<<<dim3(Nv / 64, BH), 256, FXZ_SMEM>>>(out);
}